// round 1
// baseline (speedup 1.0000x reference)
#include <cuda_runtime.h>
#include <cuda_bf16.h>

// Problem constants (fixed by the reference setup)
#define BZ 64
#define P  512
#define T  256
#define H  768
#define H4 (H / 4)   // 192 float4 per row

// Scratch: exclusive prefix sums of bert_lens per batch (device global, no alloc)
__device__ int g_start[BZ * T];

// Kernel 1: per-batch exclusive scan of lens (T=256, one block per batch)
__global__ void scan_lens_kernel(const int* __restrict__ lens) {
    __shared__ int s[T];
    const int b = blockIdx.x;
    const int t = threadIdx.x;
    int v = lens[b * T + t];
    s[t] = v;
    __syncthreads();
    // Hillis-Steele inclusive scan
    #pragma unroll
    for (int off = 1; off < T; off <<= 1) {
        int add = (t >= off) ? s[t - off] : 0;
        __syncthreads();
        s[t] += add;
        __syncthreads();
    }
    // exclusive = inclusive - own
    g_start[b * T + t] = s[t] - v;
}

// Kernel 2: one block per (b, t); 192 threads, each handles one float4 of H.
__global__ __launch_bounds__(H4) void pool_kernel(
    const float4* __restrict__ enc,   // (BZ, P, H4) float4
    const int* __restrict__ lens,     // (BZ, T)
    float4* __restrict__ out)         // (BZ, T, H4) float4
{
    const int bt = blockIdx.x;            // b*T + t
    const int b  = bt >> 8;               // T == 256
    const int h  = threadIdx.x;           // 0..191

    const int len = __ldg(&lens[bt]);

    float4 r = make_float4(0.f, 0.f, 0.f, 0.f);
    if (len > 0) {
        const int start = g_start[bt];
        const float4* row = enc + ((size_t)b * P + start) * H4 + h;
        r = __ldg(row);
        if (len == 2) {
            float4 r2 = __ldg(row + H4);
            r.x = (r.x + r2.x) * 0.5f;
            r.y = (r.y + r2.y) * 0.5f;
            r.z = (r.z + r2.z) * 0.5f;
            r.w = (r.w + r2.w) * 0.5f;
        } else if (len > 2) {
            // general fallback (not hit by this dataset, but stay correct)
            float inv = 1.0f / (float)len;
            for (int j = 1; j < len; ++j) {
                float4 r2 = __ldg(row + (size_t)j * H4);
                r.x += r2.x; r.y += r2.y; r.z += r2.z; r.w += r2.w;
            }
            r.x *= inv; r.y *= inv; r.z *= inv; r.w *= inv;
        }
    }
    out[(size_t)bt * H4 + h] = r;
}

extern "C" void kernel_launch(void* const* d_in, const int* in_sizes, int n_in,
                              void* d_out, int out_size) {
    const float* enc_out   = (const float*)d_in[0];   // (BZ, P, H) f32
    // d_in[1] = bert_mask (unused; lens fully determine the mapping)
    const int*   bert_lens = (const int*)d_in[2];     // (BZ, T) i32
    float* out = (float*)d_out;                       // (BZ, T, H) f32

    scan_lens_kernel<<<BZ, T>>>(bert_lens);
    pool_kernel<<<BZ * T, H4>>>((const float4*)enc_out, bert_lens, (float4*)out);
}

// round 2
// speedup vs baseline: 1.4337x; 1.4337x over previous
#include <cuda_runtime.h>
#include <cuda_bf16.h>

// Problem constants (fixed by the reference setup)
#define BZ 64
#define P  512
#define T  256
#define H  768
#define H4 (H / 4)   // 192 float4 per row
#define TOK_PER_BLK 8

// Scratch: packed (start | len<<16) per token (device global, no alloc)
__device__ int g_desc[BZ * T];

// Kernel 1: per-batch exclusive scan of lens, write packed descriptor
__global__ void scan_lens_kernel(const int* __restrict__ lens) {
    __shared__ int s[T];
    const int b = blockIdx.x;
    const int t = threadIdx.x;
    int v = lens[b * T + t];
    s[t] = v;
    __syncthreads();
    #pragma unroll
    for (int off = 1; off < T; off <<= 1) {
        int add = (t >= off) ? s[t - off] : 0;
        __syncthreads();
        s[t] += add;
        __syncthreads();
    }
    // exclusive start = inclusive - own; pack start (<=512) with len
    g_desc[b * T + t] = (s[t] - v) | (v << 16);
}

// Kernel 2: one warp per token; each lane handles 6 float4s of H.
__global__ __launch_bounds__(256) void pool_kernel(
    const float4* __restrict__ enc,   // (BZ, P, H4)
    float4* __restrict__ out)         // (BZ, T, H4)
{
    const int warp = threadIdx.x >> 5;
    const int lane = threadIdx.x & 31;
    const int bt   = blockIdx.x * TOK_PER_BLK + warp;  // b*T + t
    const int b    = bt >> 8;                          // T == 256

    const int desc  = g_desc[bt];                      // broadcast within warp
    const int start = desc & 0xffff;
    const int len   = desc >> 16;

    float4* obase = out + (size_t)bt * H4 + lane;

    if (len == 0) {
        const float4 z = make_float4(0.f, 0.f, 0.f, 0.f);
        #pragma unroll
        for (int i = 0; i < 6; ++i) __stcs(obase + 32 * i, z);
        return;
    }

    const float4* row = enc + ((size_t)b * P + start) * H4 + lane;

    float4 acc[6];
    #pragma unroll
    for (int i = 0; i < 6; ++i) acc[i] = __ldcs(row + 32 * i);

    if (len == 2) {
        float4 r2[6];
        #pragma unroll
        for (int i = 0; i < 6; ++i) r2[i] = __ldcs(row + H4 + 32 * i);
        #pragma unroll
        for (int i = 0; i < 6; ++i) {
            acc[i].x = (acc[i].x + r2[i].x) * 0.5f;
            acc[i].y = (acc[i].y + r2[i].y) * 0.5f;
            acc[i].z = (acc[i].z + r2[i].z) * 0.5f;
            acc[i].w = (acc[i].w + r2[i].w) * 0.5f;
        }
    } else if (len > 2) {
        // general fallback (not hit by this dataset, but stay correct)
        for (int j = 1; j < len; ++j) {
            #pragma unroll
            for (int i = 0; i < 6; ++i) {
                float4 r2 = __ldcs(row + (size_t)j * H4 + 32 * i);
                acc[i].x += r2.x; acc[i].y += r2.y;
                acc[i].z += r2.z; acc[i].w += r2.w;
            }
        }
        const float inv = 1.0f / (float)len;
        #pragma unroll
        for (int i = 0; i < 6; ++i) {
            acc[i].x *= inv; acc[i].y *= inv; acc[i].z *= inv; acc[i].w *= inv;
        }
    }

    #pragma unroll
    for (int i = 0; i < 6; ++i) __stcs(obase + 32 * i, acc[i]);
}

extern "C" void kernel_launch(void* const* d_in, const int* in_sizes, int n_in,
                              void* d_out, int out_size) {
    const float* enc_out   = (const float*)d_in[0];   // (BZ, P, H) f32
    // d_in[1] = bert_mask (unused; lens fully determine the mapping)
    const int*   bert_lens = (const int*)d_in[2];     // (BZ, T) i32
    float* out = (float*)d_out;                       // (BZ, T, H) f32

    scan_lens_kernel<<<BZ, T>>>(bert_lens);
    pool_kernel<<<(BZ * T) / TOK_PER_BLK, 256>>>((const float4*)enc_out, (float4*)out);
}

// round 4
// speedup vs baseline: 1.5550x; 1.0846x over previous
#include <cuda_runtime.h>
#include <cuda_bf16.h>

// Problem constants (fixed by the reference setup)
#define BZ 64
#define P  512
#define T  256
#define H  768
#define H4 (H / 4)       // 192 float4 per row
#define BLK_PER_B 32     // sub-blocks per batch
#define TOK_PER_BLK (T / BLK_PER_B)  // 8 tokens per block = 8 warps

// Fused kernel: each block redundantly scans its batch's lens (256 ints),
// then pools 8 tokens, one warp per token, 6 float4 per lane.
__global__ __launch_bounds__(256) void fused_pool_kernel(
    const float4* __restrict__ enc,   // (BZ, P, H4)
    const int* __restrict__ lens,     // (BZ, T)
    float4* __restrict__ out)         // (BZ, T, H4)
{
    const int warp = threadIdx.x >> 5;
    const int lane = threadIdx.x & 31;
    const int b    = blockIdx.x / BLK_PER_B;
    const int tok0 = (blockIdx.x % BLK_PER_B) * TOK_PER_BLK;

    // ---- block-wide exclusive scan of lens[b, 0..255] -> packed desc ----
    __shared__ int s_warpsum[8];
    __shared__ int s_desc[T];         // start | len<<16 per token

    const int t = threadIdx.x;        // 0..255 == token index
    int v = __ldg(&lens[b * T + t]);

    // warp-level inclusive scan
    int x = v;
    #pragma unroll
    for (int off = 1; off < 32; off <<= 1) {
        int y = __shfl_up_sync(0xffffffffu, x, off);
        if (lane >= off) x += y;
    }
    if (lane == 31) s_warpsum[warp] = x;
    __syncthreads();
    if (warp == 0 && lane < 8) {
        int w = s_warpsum[lane];
        #pragma unroll
        for (int off = 1; off < 8; off <<= 1) {
            int y = __shfl_up_sync(0xffu, w, off);
            if (lane >= off) w += y;
        }
        s_warpsum[lane] = w - s_warpsum[lane];   // exclusive warp offsets
    }
    __syncthreads();
    const int start_t = x - v + s_warpsum[warp]; // exclusive prefix for token t
    s_desc[t] = start_t | (v << 16);
    __syncthreads();

    // ---- pooling: warp handles token tok0 + warp ----
    const int tok   = tok0 + warp;
    const int desc  = s_desc[tok];
    const int start = desc & 0xffff;
    const int len   = desc >> 16;

    float4* obase = out + ((size_t)b * T + tok) * H4 + lane;

    if (len == 0) {
        const float4 z = make_float4(0.f, 0.f, 0.f, 0.f);
        #pragma unroll
        for (int i = 0; i < 6; ++i) __stcs(obase + 32 * i, z);
        return;
    }

    const float4* row = enc + ((size_t)b * P + start) * H4 + lane;

    float4 acc[6];
    #pragma unroll
    for (int i = 0; i < 6; ++i) acc[i] = __ldcs(row + 32 * i);

    if (len == 2) {
        float4 r2[6];
        #pragma unroll
        for (int i = 0; i < 6; ++i) r2[i] = __ldcs(row + H4 + 32 * i);
        #pragma unroll
        for (int i = 0; i < 6; ++i) {
            acc[i].x = (acc[i].x + r2[i].x) * 0.5f;
            acc[i].y = (acc[i].y + r2[i].y) * 0.5f;
            acc[i].z = (acc[i].z + r2[i].z) * 0.5f;
            acc[i].w = (acc[i].w + r2[i].w) * 0.5f;
        }
    } else if (len > 2) {
        // general fallback (not hit by this dataset, but stay correct)
        for (int j = 1; j < len; ++j) {
            #pragma unroll
            for (int i = 0; i < 6; ++i) {
                float4 r2 = __ldcs(row + (size_t)j * H4 + 32 * i);
                acc[i].x += r2.x; acc[i].y += r2.y;
                acc[i].z += r2.z; acc[i].w += r2.w;
            }
        }
        const float inv = 1.0f / (float)len;
        #pragma unroll
        for (int i = 0; i < 6; ++i) {
            acc[i].x *= inv; acc[i].y *= inv; acc[i].z *= inv; acc[i].w *= inv;
        }
    }

    #pragma unroll
    for (int i = 0; i < 6; ++i) __stcs(obase + 32 * i, acc[i]);
}

extern "C" void kernel_launch(void* const* d_in, const int* in_sizes, int n_in,
                              void* d_out, int out_size) {
    const float* enc_out   = (const float*)d_in[0];   // (BZ, P, H) f32
    // d_in[1] = bert_mask (unused; lens fully determine the mapping)
    const int*   bert_lens = (const int*)d_in[2];     // (BZ, T) i32
    float* out = (float*)d_out;                       // (BZ, T, H) f32

    fused_pool_kernel<<<BZ * BLK_PER_B, 256>>>(
        (const float4*)enc_out, bert_lens, (float4*)out);
}

// round 6
// speedup vs baseline: 1.9721x; 1.2682x over previous
#include <cuda_runtime.h>
#include <cuda_bf16.h>

// Problem constants (fixed by the reference setup)
#define BZ 64
#define P  512
#define T  256
#define H  768
#define H4 (H / 4)       // 192 float4 per row
#define BLK_PER_B 32     // sub-blocks per batch
#define TOK_PER_BLK (T / BLK_PER_B)  // 8 tokens per block = 8 warps

// Fused kernel: each block redundantly scans its batch's lens (256 ints),
// then pools 8 tokens, one warp per token. Per-warp work is chunked into
// 2 halves of 3 float4 to keep register count low (higher occupancy).
__global__ __launch_bounds__(256, 6) void fused_pool_kernel(
    const float4* __restrict__ enc,   // (BZ, P, H4)
    const int* __restrict__ lens,     // (BZ, T)
    float4* __restrict__ out)         // (BZ, T, H4)
{
    const int warp = threadIdx.x >> 5;
    const int lane = threadIdx.x & 31;
    const int b    = blockIdx.x / BLK_PER_B;
    const int tok0 = (blockIdx.x % BLK_PER_B) * TOK_PER_BLK;

    // ---- block-wide exclusive scan of lens[b, 0..255] -> packed desc ----
    __shared__ int s_warpsum[8];
    __shared__ int s_desc[T];         // start | len<<16 per token

    const int t = threadIdx.x;        // 0..255 == token index
    int v = __ldg(&lens[b * T + t]);

    // warp-level inclusive scan
    int x = v;
    #pragma unroll
    for (int off = 1; off < 32; off <<= 1) {
        int y = __shfl_up_sync(0xffffffffu, x, off);
        if (lane >= off) x += y;
    }
    if (lane == 31) s_warpsum[warp] = x;
    __syncthreads();
    if (warp == 0 && lane < 8) {
        int w = s_warpsum[lane];
        #pragma unroll
        for (int off = 1; off < 8; off <<= 1) {
            int y = __shfl_up_sync(0xffu, w, off);
            if (lane >= off) w += y;
        }
        s_warpsum[lane] = w - s_warpsum[lane];   // exclusive warp offsets
    }
    __syncthreads();
    const int start_t = x - v + s_warpsum[warp]; // exclusive prefix for token t
    s_desc[t] = start_t | (v << 16);
    __syncthreads();

    // ---- pooling: warp handles token tok0 + warp ----
    const int tok   = tok0 + warp;
    const int desc  = s_desc[tok];
    const int start = desc & 0xffff;
    const int len   = desc >> 16;

    float4* obase = out + ((size_t)b * T + tok) * H4 + lane;

    if (len == 0) {
        const float4 z = make_float4(0.f, 0.f, 0.f, 0.f);
        #pragma unroll
        for (int i = 0; i < 6; ++i) __stcs(obase + 32 * i, z);
        return;
    }

    const float4* row = enc + ((size_t)b * P + start) * H4 + lane;

    if (len == 1) {
        #pragma unroll
        for (int half = 0; half < 2; ++half) {
            float4 a0 = row[96 * half + 0];
            float4 a1 = row[96 * half + 32];
            float4 a2 = row[96 * half + 64];
            __stcs(obase + 96 * half + 0,  a0);
            __stcs(obase + 96 * half + 32, a1);
            __stcs(obase + 96 * half + 64, a2);
        }
    } else if (len == 2) {
        #pragma unroll
        for (int half = 0; half < 2; ++half) {
            float4 a0 = row[96 * half + 0];
            float4 a1 = row[96 * half + 32];
            float4 a2 = row[96 * half + 64];
            float4 b0 = row[H4 + 96 * half + 0];
            float4 b1 = row[H4 + 96 * half + 32];
            float4 b2 = row[H4 + 96 * half + 64];
            a0.x = (a0.x + b0.x) * 0.5f; a0.y = (a0.y + b0.y) * 0.5f;
            a0.z = (a0.z + b0.z) * 0.5f; a0.w = (a0.w + b0.w) * 0.5f;
            a1.x = (a1.x + b1.x) * 0.5f; a1.y = (a1.y + b1.y) * 0.5f;
            a1.z = (a1.z + b1.z) * 0.5f; a1.w = (a1.w + b1.w) * 0.5f;
            a2.x = (a2.x + b2.x) * 0.5f; a2.y = (a2.y + b2.y) * 0.5f;
            a2.z = (a2.z + b2.z) * 0.5f; a2.w = (a2.w + b2.w) * 0.5f;
            __stcs(obase + 96 * half + 0,  a0);
            __stcs(obase + 96 * half + 32, a1);
            __stcs(obase + 96 * half + 64, a2);
        }
    } else {
        // general fallback (not hit by this dataset, but stay correct)
        const float inv = 1.0f / (float)len;
        #pragma unroll
        for (int half = 0; half < 2; ++half) {
            #pragma unroll
            for (int i = 0; i < 3; ++i) {
                const int off = 96 * half + 32 * i;
                float4 acc = row[off];
                for (int j = 1; j < len; ++j) {
                    float4 r2 = row[(size_t)j * H4 + off];
                    acc.x += r2.x; acc.y += r2.y; acc.z += r2.z; acc.w += r2.w;
                }
                acc.x *= inv; acc.y *= inv; acc.z *= inv; acc.w *= inv;
                __stcs(obase + off, acc);
            }
        }
    }
}

extern "C" void kernel_launch(void* const* d_in, const int* in_sizes, int n_in,
                              void* d_out, int out_size) {
    const float* enc_out   = (const float*)d_in[0];   // (BZ, P, H) f32
    // d_in[1] = bert_mask (unused; lens fully determine the mapping)
    const int*   bert_lens = (const int*)d_in[2];     // (BZ, T) i32
    float* out = (float*)d_out;                       // (BZ, T, H) f32

    fused_pool_kernel<<<BZ * BLK_PER_B, 256>>>(
        (const float4*)enc_out, bert_lens, (float4*)out);
}